// round 9
// baseline (speedup 1.0000x reference)
#include <cuda_runtime.h>
#include <cuda_fp16.h>
#include <cstdint>

#define Bn  256
#define Vn  2048
#define PDn 1024
#define MDn 512
#define Hn  512
#define W1LD (PDn + MDn)

typedef unsigned long long u64;

// Intermediates (device globals; no allocations).
__device__ __half g_hm[Vn * Hn];    // [v][h]
__device__ __half g_hpH[Bn * Hn];   // [b][h], b1 folded

__device__ __forceinline__ unsigned tanh2_f16(unsigned x) {
    unsigned y;
    asm("tanh.approx.f16x2 %0, %1;" : "=r"(y) : "r"(x));
    return y;
}
__device__ __forceinline__ unsigned hadd2u(unsigned a, unsigned b) {
    unsigned d;
    asm("add.rn.f16x2 %0, %1, %2;" : "=r"(d) : "r"(a), "r"(b));
    return d;
}
__device__ __forceinline__ u64 mul2d(u64 a, u64 b) {
    u64 d; asm("mul.rn.f32x2 %0,%1,%2;" : "=l"(d) : "l"(a), "l"(b)); return d;
}
__device__ __forceinline__ u64 fma2d(u64 a, u64 b, u64 c) {
    u64 d; asm("fma.rn.f32x2 %0,%1,%2,%3;" : "=l"(d) : "l"(a), "l"(b), "l"(c)); return d;
}
__device__ __forceinline__ u64 dup32(float f) {
    unsigned u = __float_as_uint(f);
    return ((u64)u << 32) | u;
}

// Accurate tanh on the FMA pipe (XLA minimax rational [13/6], |x|<=9,
// err ~1e-6). f32x2 packed; reciprocal = bit-trick + 2 Newton (no MUFU).
__device__ __forceinline__ unsigned tanh2_poly(unsigned xu) {
    __half2 xh = *(__half2*)&xu;
    xh = __hmin2(__hmax2(xh, __float2half2_rn(-7.9f)), __float2half2_rn(7.9f));
    float2 f = __half22float2(xh);
    u64 x; asm("mov.b64 %0,{%1,%2};" : "=l"(x) : "f"(f.x), "f"(f.y));
    u64 t = mul2d(x, x);
    u64 num = fma2d(t, dup32(-2.76076847742355e-16f), dup32(2.00018790482477e-13f));
    num = fma2d(t, num, dup32(-8.60467152213735e-11f));
    num = fma2d(t, num, dup32( 5.12229709037114e-08f));
    num = fma2d(t, num, dup32( 1.48572235717979e-05f));
    num = fma2d(t, num, dup32( 6.37261928875436e-04f));
    num = fma2d(t, num, dup32( 4.89352455891786e-03f));
    num = mul2d(num, x);
    u64 den = fma2d(t, dup32(1.19825839466702e-06f), dup32(1.18534705686654e-04f));
    den = fma2d(t, den, dup32(2.26843463243900e-03f));
    den = fma2d(t, den, dup32(4.89352518554385e-03f));
    unsigned dlo, dhi;
    asm("mov.b64 {%0,%1},%2;" : "=r"(dlo), "=r"(dhi) : "l"(den));
    unsigned rlo = 0x7EF311C3u - dlo, rhi = 0x7EF311C3u - dhi;
    u64 r; asm("mov.b64 %0,{%1,%2};" : "=l"(r) : "r"(rlo), "r"(rhi));
    const u64 TWO = dup32(2.0f), NEG1 = dup32(-1.0f);
    r = mul2d(r, fma2d(mul2d(den, r), NEG1, TWO));
    r = mul2d(r, fma2d(mul2d(den, r), NEG1, TWO));
    u64 res = mul2d(num, r);
    float g0, g1;
    asm("mov.b64 {%0,%1},%2;" : "=f"(g0), "=f"(g1) : "l"(res));
    unsigned out;
    asm("cvt.rn.f16x2.f32 %0,%1,%2;" : "=r"(out) : "f"(g1), "f"(g0));
    return out;
}

__device__ __forceinline__ void mma_16816(float c[4],
    unsigned a0, unsigned a1, unsigned a2, unsigned a3,
    unsigned b0, unsigned b1)
{
    asm volatile(
        "mma.sync.aligned.m16n8k16.row.col.f32.f16.f16.f32 "
        "{%0,%1,%2,%3}, {%4,%5,%6,%7}, {%8,%9}, {%0,%1,%2,%3};"
        : "+f"(c[0]), "+f"(c[1]), "+f"(c[2]), "+f"(c[3])
        : "r"(a0), "r"(a1), "r"(a2), "r"(a3), "r"(b0), "r"(b1));
}

// ---------------------------------------------------------------------------
// HMMA GEMM, inline fp32->fp16 convert. 144 blocks (single wave) x 256 thr,
// tile 128m x 64h:  bid<128: hm (K=512);  bid>=128: hp (K=1024, b1 folded).
// Warp tile 32m x 32n (2x4 mma). smem rows stride 72 halves (conflict-free).
// ---------------------------------------------------------------------------
__global__ void __launch_bounds__(256) hmma_gemm_kernel(
    const float* __restrict__ patient,
    const float* __restrict__ atc4,
    const float* __restrict__ W1,
    const float* __restrict__ b1)
{
    __shared__ __half As[128 * 72];  // 18 KB
    __shared__ __half Ws[64 * 72];   // 9 KB

    const int bid = blockIdx.x;
    const int tid = threadIdx.x;

    const float* A;
    int LDA, m0, n0, kW0, KLEN;
    bool is_hp;
    if (bid < 128) {
        A = atc4;  LDA = MDn;
        m0 = (bid & 15) * 128;  n0 = (bid >> 4) * 64;
        kW0 = PDn;  KLEN = MDn;  is_hp = false;
    } else {
        int t = bid - 128;      // 0..15
        A = patient;  LDA = PDn;
        m0 = (t & 1) * 128;  n0 = (t >> 1) * 64;
        kW0 = 0;  KLEN = PDn;  is_hp = true;
    }

    const int wid = tid >> 5, lane = tid & 31;
    const int g = lane >> 2, t4 = lane & 3;
    const int wm = wid & 3, wn = wid >> 2;

    float acc[2][4][4];
    #pragma unroll
    for (int i = 0; i < 2; i++)
        #pragma unroll
        for (int j = 0; j < 4; j++)
            #pragma unroll
            for (int c = 0; c < 4; c++) acc[i][j][c] = 0.0f;

    float4 fA[8], fW[4];
    auto ldg = [&](int k0) {
        #pragma unroll
        for (int it = 0; it < 8; it++) {
            int idx = tid + it * 256, r = idx >> 4, q = idx & 15;
            fA[it] = *(const float4*)(A + (size_t)(m0 + r) * LDA + k0 + q * 4);
        }
        #pragma unroll
        for (int it = 0; it < 4; it++) {
            int idx = tid + it * 256, r = idx >> 4, q = idx & 15;
            fW[it] = *(const float4*)(W1 + (size_t)(n0 + r) * W1LD + kW0 + k0 + q * 4);
        }
    };
    auto sts = [&]() {
        #pragma unroll
        for (int it = 0; it < 8; it++) {
            int idx = tid + it * 256, r = idx >> 4, q = idx & 15;
            __half h4[4] = { __float2half_rn(fA[it].x), __float2half_rn(fA[it].y),
                             __float2half_rn(fA[it].z), __float2half_rn(fA[it].w) };
            *(uint2*)&As[r * 72 + q * 4] = *(uint2*)h4;
        }
        #pragma unroll
        for (int it = 0; it < 4; it++) {
            int idx = tid + it * 256, r = idx >> 4, q = idx & 15;
            __half h4[4] = { __float2half_rn(fW[it].x), __float2half_rn(fW[it].y),
                             __float2half_rn(fW[it].z), __float2half_rn(fW[it].w) };
            *(uint2*)&Ws[r * 72 + q * 4] = *(uint2*)h4;
        }
    };

    const int NCH = KLEN / 64;
    ldg(0);
    sts();
    if (NCH > 1) ldg(64);
    __syncthreads();

    for (int c = 0; c < NCH; c++) {
        #pragma unroll
        for (int ks = 0; ks < 4; ks++) {
            const int kb = ks * 16;
            unsigned a[2][4], b[4][2];
            #pragma unroll
            for (int i = 0; i < 2; i++) {
                int r0 = wm * 32 + i * 16 + g, r1 = r0 + 8;
                a[i][0] = *(const unsigned*)&As[r0 * 72 + kb + 2 * t4];
                a[i][1] = *(const unsigned*)&As[r1 * 72 + kb + 2 * t4];
                a[i][2] = *(const unsigned*)&As[r0 * 72 + kb + 2 * t4 + 8];
                a[i][3] = *(const unsigned*)&As[r1 * 72 + kb + 2 * t4 + 8];
            }
            #pragma unroll
            for (int j = 0; j < 4; j++) {
                int n = wn * 32 + j * 8 + g;
                b[j][0] = *(const unsigned*)&Ws[n * 72 + kb + 2 * t4];
                b[j][1] = *(const unsigned*)&Ws[n * 72 + kb + 2 * t4 + 8];
            }
            #pragma unroll
            for (int i = 0; i < 2; i++)
                #pragma unroll
                for (int j = 0; j < 4; j++)
                    mma_16816(acc[i][j], a[i][0], a[i][1], a[i][2], a[i][3],
                              b[j][0], b[j][1]);
        }
        __syncthreads();
        if (c + 1 < NCH) {
            sts();
            if (c + 2 < NCH) ldg((c + 2) * 64);
            __syncthreads();
        }
    }

    __half* dst = is_hp ? g_hpH : g_hm;
    #pragma unroll
    for (int i = 0; i < 2; i++) {
        int r0 = m0 + wm * 32 + i * 16 + g, r1 = r0 + 8;
        #pragma unroll
        for (int j = 0; j < 4; j++) {
            int cn = n0 + wn * 32 + j * 8 + 2 * t4;
            float x0 = acc[i][j][0], x1 = acc[i][j][1];
            float x2 = acc[i][j][2], x3 = acc[i][j][3];
            if (is_hp) {
                float2 bb = *(const float2*)&b1[cn];
                x0 += bb.x; x1 += bb.y; x2 += bb.x; x3 += bb.y;
            }
            *(__half2*)&dst[(size_t)r0 * Hn + cn] = __floats2half2_rn(x0, x1);
            *(__half2*)&dst[(size_t)r1 * Hn + cn] = __floats2half2_rn(x2, x3);
        }
    }
}

// ---------------------------------------------------------------------------
// Score: out[b,v] = b2 + sum_h w2[h]*tanh(hp[b,h]+hm[v,h]).
// Hybrid tanh: 10/32 of (c,b) iterations use the FMA-pipe rational (runs in
// parallel with the MUFU pipe); rest use MUFU f16x2 tanh. Both feed HMMA
// fp32 accumulation. Block 128 thr, tile 64v x 8b, grid 1024.
// ---------------------------------------------------------------------------
__global__ void __launch_bounds__(128) score_kernel(
    const float* __restrict__ w2, const float* __restrict__ b2p,
    float* __restrict__ out)
{
    __shared__ __half hm_sh[64 * 72];
    __shared__ __half hp_sh[8 * 72];
    __shared__ __half w2h_sh[Hn];

    const int tid  = threadIdx.x;
    const int v0   = blockIdx.x * 64;
    const int b0   = blockIdx.y * 8;
    const int lane = tid & 31;
    const int g    = lane >> 2;
    const int t    = lane & 3;
    const int vbase = (tid >> 5) * 16;

    {   // w2 -> fp16 once (covered by first __syncthreads)
        float4 w = ((const float4*)w2)[tid];
        __half h4[4] = { __float2half_rn(w.x), __float2half_rn(w.y),
                         __float2half_rn(w.z), __float2half_rn(w.w) };
        *(uint2*)&w2h_sh[tid * 4] = *(uint2*)h4;
    }

    float acc[8][4];
    #pragma unroll
    for (int b = 0; b < 8; b++)
        #pragma unroll
        for (int c = 0; c < 4; c++) acc[b][c] = 0.0f;

    for (int h0 = 0; h0 < Hn; h0 += 64) {
        __syncthreads();
        #pragma unroll
        for (int r = 0; r < 4; r++) {   // hm [64v x 64h]
            int idx = tid + r * 128;
            int vv = idx >> 3, q = idx & 7;
            uint4 m = *(const uint4*)(g_hm + (size_t)(v0 + vv) * Hn + h0 + q * 8);
            *(uint4*)&hm_sh[vv * 72 + q * 8] = m;
        }
        if (tid < 64) {                 // hp [8b x 64h] direct copy (b1 folded)
            int b = tid >> 3, q = tid & 7;
            uint4 m = *(const uint4*)(g_hpH + (size_t)(b0 + b) * Hn + h0 + q * 8);
            *(uint4*)&hp_sh[b * 72 + q * 8] = m;
        }
        __syncthreads();

        const __half* hmr0 = &hm_sh[(vbase + g) * 72];
        const __half* hmr1 = &hm_sh[(vbase + g + 8) * 72];

        #pragma unroll
        for (int c = 0; c < 4; c++) {
            const int hb = c * 16;
            unsigned m00 = *(const unsigned*)&hmr0[hb + 2 * t];
            unsigned m10 = *(const unsigned*)&hmr1[hb + 2 * t];
            unsigned m01 = *(const unsigned*)&hmr0[hb + 2 * t + 8];
            unsigned m11 = *(const unsigned*)&hmr1[hb + 2 * t + 8];
            unsigned bw0 = *(const unsigned*)&w2h_sh[h0 + hb + 2 * t];
            unsigned bw1 = *(const unsigned*)&w2h_sh[h0 + hb + 2 * t + 8];
            #pragma unroll
            for (int b = 0; b < 8; b++) {
                unsigned p0 = *(const unsigned*)&hp_sh[b * 72 + hb + 2 * t];
                unsigned p1 = *(const unsigned*)&hp_sh[b * 72 + hb + 2 * t + 8];
                unsigned x0 = hadd2u(m00, p0);
                unsigned x1 = hadd2u(m10, p0);
                unsigned x2 = hadd2u(m01, p1);
                unsigned x3 = hadd2u(m11, p1);
                unsigned a0, a1, a2, a3;
                if (c == 3 || (c == 2 && b < 2)) {   // 10/32 on FMA pipe
                    a0 = tanh2_poly(x0); a1 = tanh2_poly(x1);
                    a2 = tanh2_poly(x2); a3 = tanh2_poly(x3);
                } else {                              // 22/32 on MUFU pipe
                    a0 = tanh2_f16(x0); a1 = tanh2_f16(x1);
                    a2 = tanh2_f16(x2); a3 = tanh2_f16(x3);
                }
                mma_16816(acc[b], a0, a1, a2, a3, bw0, bw1);
            }
        }
    }

    const float b2 = *b2p;
    if (t == 0) {
        #pragma unroll
        for (int b = 0; b < 8; b++) {
            out[(size_t)(b0 + b) * Vn + v0 + vbase + g]     = acc[b][0] + b2;
            out[(size_t)(b0 + b) * Vn + v0 + vbase + g + 8] = acc[b][2] + b2;
        }
    }
}

extern "C" void kernel_launch(void* const* d_in, const int* in_sizes, int n_in,
                              void* d_out, int out_size) {
    const float* patient = (const float*)d_in[0];  // [B, PD]
    const float* atc4    = (const float*)d_in[1];  // [V, MD]
    const float* W1      = (const float*)d_in[2];  // [H, PD+MD]
    const float* b1      = (const float*)d_in[3];  // [H]
    const float* w2      = (const float*)d_in[4];  // [H]
    const float* b2      = (const float*)d_in[5];  // scalar
    float* out = (float*)d_out;                    // [B, V]

    hmma_gemm_kernel<<<144, 256>>>(patient, atc4, W1, b1);

    dim3 grid(Vn / 64, Bn / 8);    // 1024 blocks
    score_kernel<<<grid, 128>>>(w2, b2, out);
}

// round 10
// speedup vs baseline: 1.3783x; 1.3783x over previous
#include <cuda_runtime.h>
#include <cuda_fp16.h>
#include <cstdint>

#define Bn  256
#define Vn  2048
#define PDn 1024
#define MDn 512
#define Hn  512
#define W1LD (PDn + MDn)

// Intermediates (device globals; no allocations).
__device__ __half g_hm[Vn * Hn];          // [v][h]
__device__ __half g_hp2[2 * Bn * Hn];     // two split-K slices, [b][h]; b1 in slice 0

__device__ __forceinline__ unsigned tanh2_f16(unsigned x) {
    unsigned y;
    asm("tanh.approx.f16x2 %0, %1;" : "=r"(y) : "r"(x));
    return y;
}
__device__ __forceinline__ unsigned hadd2u(unsigned a, unsigned b) {
    unsigned d;
    asm("add.rn.f16x2 %0, %1, %2;" : "=r"(d) : "r"(a), "r"(b));
    return d;
}

// tanh on the FMA pipe: pure f16x2 HFMA2 chain, 12 ops, no cvt/mov/div.
// y = xc * P(s), xc = clamp(x, +-2.75), s = xc^2/3.78125 - 1 in [-1,1].
// Degree-7 Chebyshev fit of tanh(sqrt(u))/sqrt(u); verified max err ~2e-4.
// |x|>2.75 -> tanh(2.75)=0.9919 (tail mass ~4e-4, negligible in norm).
__device__ __forceinline__ unsigned tanh2_fma(unsigned xu) {
    __half2 x = *(__half2*)&xu;
    __half2 xc = __hmin2(__hmax2(x, __float2half2_rn(-2.75f)),
                         __float2half2_rn(2.75f));
    __half2 u = __hmul2(xc, xc);
    __half2 s = __hfma2(u, __float2half2_rn(0.26446280f),
                           __float2half2_rn(-1.0f));
    __half2 p = __hfma2(__float2half2_rn(-0.0224000f), s,
                        __float2half2_rn( 0.0371840f));
    p = __hfma2(p, s, __float2half2_rn(-0.0164160f));
    p = __hfma2(p, s, __float2half2_rn( 0.0272720f));
    p = __hfma2(p, s, __float2half2_rn(-0.0733200f));
    p = __hfma2(p, s, __float2half2_rn( 0.1221940f));
    p = __hfma2(p, s, __float2half2_rn(-0.2074220f));
    p = __hfma2(p, s, __float2half2_rn( 0.4935290f));
    __half2 y = __hmul2(xc, p);
    return *(unsigned*)&y;
}

__device__ __forceinline__ void mma_16816(float c[4],
    unsigned a0, unsigned a1, unsigned a2, unsigned a3,
    unsigned b0, unsigned b1)
{
    asm volatile(
        "mma.sync.aligned.m16n8k16.row.col.f32.f16.f16.f32 "
        "{%0,%1,%2,%3}, {%4,%5,%6,%7}, {%8,%9}, {%0,%1,%2,%3};"
        : "+f"(c[0]), "+f"(c[1]), "+f"(c[2]), "+f"(c[3])
        : "r"(a0), "r"(a1), "r"(a2), "r"(a3), "r"(b0), "r"(b1));
}

// ---------------------------------------------------------------------------
// HMMA GEMM with inline fp32->fp16 conversion (R8 verbatim, measured 13.1us).
// 320 blocks x 256 thr, tile 64m x 64h, K=512 per block.
// ---------------------------------------------------------------------------
__global__ void __launch_bounds__(256) hmma_gemm_kernel(
    const float* __restrict__ patient,
    const float* __restrict__ atc4,
    const float* __restrict__ W1,
    const float* __restrict__ b1)
{
    __shared__ __half As[64 * 72];
    __shared__ __half Ws[64 * 72];

    const int bid = blockIdx.x;
    const int tid = threadIdx.x;

    const float* A;
    __half* dst;
    int LDA, m0, n0, kA0, kW0;
    bool add_b1;

    if (bid < 256) {                  // hm
        A = atc4;  LDA = MDn;  dst = g_hm;
        m0 = (bid & 31) * 64;
        n0 = (bid >> 5) * 64;
        kA0 = 0;  kW0 = PDn;
        add_b1 = false;
    } else {                          // hp split-K2
        int t = bid - 256;
        int s = t & 1;
        A = patient;  LDA = PDn;  dst = g_hp2 + s * (Bn * Hn);
        m0 = ((t >> 1) & 3) * 64;
        n0 = (t >> 3) * 64;
        kA0 = s * 512;  kW0 = s * 512;
        add_b1 = (s == 0);
    }

    const int wid = tid >> 5, lane = tid & 31;
    const int g = lane >> 2, t4 = lane & 3;
    const int wm = wid & 1, wn = wid >> 1;

    float acc[2][2][4];
    #pragma unroll
    for (int i = 0; i < 2; i++)
        #pragma unroll
        for (int j = 0; j < 2; j++)
            #pragma unroll
            for (int c = 0; c < 4; c++) acc[i][j][c] = 0.0f;

    const int sr = tid >> 4;
    const int sq = tid & 15;

    float4 fA[4], fW[4];
    auto ldg = [&](int k0) {
        #pragma unroll
        for (int it = 0; it < 4; it++) {
            int r = sr + it * 16;
            fA[it] = *(const float4*)(A  + (size_t)(m0 + r) * LDA  + kA0 + k0 + sq * 4);
            fW[it] = *(const float4*)(W1 + (size_t)(n0 + r) * W1LD + kW0 + k0 + sq * 4);
        }
    };
    auto sts = [&]() {
        #pragma unroll
        for (int it = 0; it < 4; it++) {
            int r = sr + it * 16;
            __half ha[4] = { __float2half_rn(fA[it].x), __float2half_rn(fA[it].y),
                             __float2half_rn(fA[it].z), __float2half_rn(fA[it].w) };
            __half hw[4] = { __float2half_rn(fW[it].x), __float2half_rn(fW[it].y),
                             __float2half_rn(fW[it].z), __float2half_rn(fW[it].w) };
            *(uint2*)&As[r * 72 + sq * 4] = *(uint2*)ha;
            *(uint2*)&Ws[r * 72 + sq * 4] = *(uint2*)hw;
        }
    };

    const int NCH = 512 / 64;
    ldg(0);
    sts();
    ldg(64);
    __syncthreads();

    for (int c = 0; c < NCH; c++) {
        #pragma unroll
        for (int ks = 0; ks < 4; ks++) {
            const int kb = ks * 16;
            unsigned a[2][4], b[2][2];
            #pragma unroll
            for (int i = 0; i < 2; i++) {
                int r0 = wm * 32 + i * 16 + g, r1 = r0 + 8;
                a[i][0] = *(const unsigned*)&As[r0 * 72 + kb + 2 * t4];
                a[i][1] = *(const unsigned*)&As[r1 * 72 + kb + 2 * t4];
                a[i][2] = *(const unsigned*)&As[r0 * 72 + kb + 2 * t4 + 8];
                a[i][3] = *(const unsigned*)&As[r1 * 72 + kb + 2 * t4 + 8];
            }
            #pragma unroll
            for (int j = 0; j < 2; j++) {
                int n = wn * 16 + j * 8 + g;
                b[j][0] = *(const unsigned*)&Ws[n * 72 + kb + 2 * t4];
                b[j][1] = *(const unsigned*)&Ws[n * 72 + kb + 2 * t4 + 8];
            }
            #pragma unroll
            for (int i = 0; i < 2; i++)
                #pragma unroll
                for (int j = 0; j < 2; j++)
                    mma_16816(acc[i][j], a[i][0], a[i][1], a[i][2], a[i][3],
                              b[j][0], b[j][1]);
        }
        __syncthreads();
        if (c + 1 < NCH) {
            sts();
            if (c + 2 < NCH) ldg((c + 2) * 64);
            __syncthreads();
        }
    }

    #pragma unroll
    for (int i = 0; i < 2; i++) {
        int r0 = m0 + wm * 32 + i * 16 + g, r1 = r0 + 8;
        #pragma unroll
        for (int j = 0; j < 2; j++) {
            int cn = n0 + wn * 16 + j * 8 + 2 * t4;
            float x0 = acc[i][j][0], x1 = acc[i][j][1];
            float x2 = acc[i][j][2], x3 = acc[i][j][3];
            if (add_b1) {
                float2 bb = *(const float2*)&b1[cn];
                x0 += bb.x; x1 += bb.y; x2 += bb.x; x3 += bb.y;
            }
            *(__half2*)&dst[(size_t)r0 * Hn + cn] = __floats2half2_rn(x0, x1);
            *(__half2*)&dst[(size_t)r1 * Hn + cn] = __floats2half2_rn(x2, x3);
        }
    }
}

// ---------------------------------------------------------------------------
// Score (R8 structure): out[b,v] = b2 + sum_h w2[h]*tanh(hp[b,h]+hm[v,h]).
// ONLY change vs R8: hybrid tanh routing — regs a0,a2 (and a3 on odd b) on
// MUFU; reg a1 (and a3 on even b) on the FMA-pipe HFMA2 poly. MUFU 40cyc vs
// FMA 44cyc per iteration -> both pipes ~balanced, T/iter 64 -> ~44.
// ---------------------------------------------------------------------------
__global__ void __launch_bounds__(128, 8) score_kernel(
    const float* __restrict__ w2, const float* __restrict__ b2p,
    float* __restrict__ out)
{
    __shared__ __half hm_sh[64 * 72];
    __shared__ __half hp_sh[8 * 72];
    __shared__ __half w2h_sh[Hn];

    const int tid  = threadIdx.x;
    const int v0   = blockIdx.x * 64;
    const int b0   = blockIdx.y * 8;
    const int lane = tid & 31;
    const int g    = lane >> 2;
    const int t    = lane & 3;
    const int vbase = (tid >> 5) * 16;

    {   // w2 -> fp16 once (covered by first __syncthreads)
        float4 w = ((const float4*)w2)[tid];
        __half h4[4] = { __float2half_rn(w.x), __float2half_rn(w.y),
                         __float2half_rn(w.z), __float2half_rn(w.w) };
        *(uint2*)&w2h_sh[tid * 4] = *(uint2*)h4;
    }

    float acc[8][4];
    #pragma unroll
    for (int b = 0; b < 8; b++)
        #pragma unroll
        for (int c = 0; c < 4; c++) acc[b][c] = 0.0f;

    for (int h0 = 0; h0 < Hn; h0 += 64) {
        __syncthreads();
        #pragma unroll
        for (int r = 0; r < 4; r++) {   // hm [64v x 64h]
            int idx = tid + r * 128;
            int vv = idx >> 3, q = idx & 7;
            uint4 m = *(const uint4*)(g_hm + (size_t)(v0 + vv) * Hn + h0 + q * 8);
            *(uint4*)&hm_sh[vv * 72 + q * 8] = m;
        }
        if (tid < 64) {                 // hp [8b x 64h] = slice0 + slice1
            int b = tid >> 3, q = tid & 7;
            size_t off = (size_t)(b0 + b) * Hn + h0 + q * 8;
            uint4 x = *(const uint4*)(g_hp2 + off);
            uint4 y = *(const uint4*)(g_hp2 + Bn * Hn + off);
            uint4 z;
            z.x = hadd2u(x.x, y.x);  z.y = hadd2u(x.y, y.y);
            z.z = hadd2u(x.z, y.z);  z.w = hadd2u(x.w, y.w);
            *(uint4*)&hp_sh[b * 72 + q * 8] = z;
        }
        __syncthreads();

        const __half* hmr0 = &hm_sh[(vbase + g) * 72];
        const __half* hmr1 = &hm_sh[(vbase + g + 8) * 72];

        #pragma unroll
        for (int c = 0; c < 4; c++) {
            const int hb = c * 16;
            unsigned m00 = *(const unsigned*)&hmr0[hb + 2 * t];
            unsigned m10 = *(const unsigned*)&hmr1[hb + 2 * t];
            unsigned m01 = *(const unsigned*)&hmr0[hb + 2 * t + 8];
            unsigned m11 = *(const unsigned*)&hmr1[hb + 2 * t + 8];
            unsigned bw0 = *(const unsigned*)&w2h_sh[h0 + hb + 2 * t];
            unsigned bw1 = *(const unsigned*)&w2h_sh[h0 + hb + 2 * t + 8];
            #pragma unroll
            for (int b = 0; b < 8; b++) {
                unsigned p0 = *(const unsigned*)&hp_sh[b * 72 + hb + 2 * t];
                unsigned p1 = *(const unsigned*)&hp_sh[b * 72 + hb + 2 * t + 8];
                unsigned x0 = hadd2u(m00, p0);
                unsigned x1 = hadd2u(m10, p0);
                unsigned x2 = hadd2u(m01, p1);
                unsigned x3 = hadd2u(m11, p1);
                // Hybrid routing: 2.5 regs MUFU, 1.5 regs FMA-pipe poly.
                unsigned a0 = tanh2_f16(x0);
                unsigned a1 = tanh2_fma(x1);
                unsigned a2 = tanh2_f16(x2);
                unsigned a3 = ((b & 1) == 0) ? tanh2_fma(x3) : tanh2_f16(x3);
                mma_16816(acc[b], a0, a1, a2, a3, bw0, bw1);
            }
        }
    }

    const float b2 = *b2p;
    if (t == 0) {
        #pragma unroll
        for (int b = 0; b < 8; b++) {
            out[(size_t)(b0 + b) * Vn + v0 + vbase + g]     = acc[b][0] + b2;
            out[(size_t)(b0 + b) * Vn + v0 + vbase + g + 8] = acc[b][2] + b2;
        }
    }
}

extern "C" void kernel_launch(void* const* d_in, const int* in_sizes, int n_in,
                              void* d_out, int out_size) {
    const float* patient = (const float*)d_in[0];  // [B, PD]
    const float* atc4    = (const float*)d_in[1];  // [V, MD]
    const float* W1      = (const float*)d_in[2];  // [H, PD+MD]
    const float* b1      = (const float*)d_in[3];  // [H]
    const float* w2      = (const float*)d_in[4];  // [H]
    const float* b2      = (const float*)d_in[5];  // scalar
    float* out = (float*)d_out;                    // [B, V]

    hmma_gemm_kernel<<<320, 256>>>(patient, atc4, W1, b1);

    dim3 grid(Vn / 64, Bn / 8);    // 1024 blocks
    score_kernel<<<grid, 128>>>(w2, b2, out);
}

// round 11
// speedup vs baseline: 1.4091x; 1.0223x over previous
#include <cuda_runtime.h>
#include <cuda_fp16.h>
#include <cstdint>

#define Bn  256
#define Vn  2048
#define PDn 1024
#define MDn 512
#define Hn  512
#define W1LD (PDn + MDn)

#define GTP 40   // GEMM smem row stride (halves): LDSM phases hit all 32 banks

// Intermediates (device globals; no allocations).
__device__ __half g_hm[Vn * Hn];          // [v][h]
__device__ __half g_hp2[2 * Bn * Hn];     // split-K2 slices, [b][h]; b1 in slice 0

__device__ __forceinline__ unsigned tanh2_f16(unsigned x) {
    unsigned y;
    asm("tanh.approx.f16x2 %0, %1;" : "=r"(y) : "r"(x));
    return y;
}
__device__ __forceinline__ unsigned hadd2u(unsigned a, unsigned b) {
    unsigned d;
    asm("add.rn.f16x2 %0, %1, %2;" : "=r"(d) : "r"(a), "r"(b));
    return d;
}

// tanh on the FMA pipe (R10-proven): 12 f16x2 ops, no cvt/mov/div.
__device__ __forceinline__ unsigned tanh2_fma(unsigned xu) {
    __half2 x = *(__half2*)&xu;
    __half2 xc = __hmin2(__hmax2(x, __float2half2_rn(-2.75f)),
                         __float2half2_rn(2.75f));
    __half2 u = __hmul2(xc, xc);
    __half2 s = __hfma2(u, __float2half2_rn(0.26446280f),
                           __float2half2_rn(-1.0f));
    __half2 p = __hfma2(__float2half2_rn(-0.0224000f), s,
                        __float2half2_rn( 0.0371840f));
    p = __hfma2(p, s, __float2half2_rn(-0.0164160f));
    p = __hfma2(p, s, __float2half2_rn( 0.0272720f));
    p = __hfma2(p, s, __float2half2_rn(-0.0733200f));
    p = __hfma2(p, s, __float2half2_rn( 0.1221940f));
    p = __hfma2(p, s, __float2half2_rn(-0.2074220f));
    p = __hfma2(p, s, __float2half2_rn( 0.4935290f));
    __half2 y = __hmul2(xc, p);
    return *(unsigned*)&y;
}

__device__ __forceinline__ void mma_16816(float c[4],
    unsigned a0, unsigned a1, unsigned a2, unsigned a3,
    unsigned b0, unsigned b1)
{
    asm volatile(
        "mma.sync.aligned.m16n8k16.row.col.f32.f16.f16.f32 "
        "{%0,%1,%2,%3}, {%4,%5,%6,%7}, {%8,%9}, {%0,%1,%2,%3};"
        : "+f"(c[0]), "+f"(c[1]), "+f"(c[2]), "+f"(c[3])
        : "r"(a0), "r"(a1), "r"(a2), "r"(a3), "r"(b0), "r"(b1));
}
__device__ __forceinline__ void ldsm_x4(unsigned& r0, unsigned& r1,
                                        unsigned& r2, unsigned& r3,
                                        unsigned addr) {
    asm volatile("ldmatrix.sync.aligned.m8n8.x4.shared.b16 {%0,%1,%2,%3}, [%4];"
        : "=r"(r0), "=r"(r1), "=r"(r2), "=r"(r3) : "r"(addr));
}

// ---------------------------------------------------------------------------
// HMMA GEMM, ldmatrix fragments, inline fp32->fp16 convert.
// 80 uniform blocks x 256 thr, tile 128m x 128h, K=512 (single wave):
//   bid < 64 : hm (16 v-tiles x 4 h-tiles)            -> g_hm
//   bid >= 64: hp (2 b-tiles x 4 h-tiles x splitK2)   -> g_hp2[s]
// Warp tile 64m x 32n = 4x4 mma(m16n8k16). Double-buffered smem, k-chunk 32,
// LDG pipelined 2 chunks ahead, 1 sync/chunk. Row stride GTP=40 halves.
// ---------------------------------------------------------------------------
__global__ void __launch_bounds__(256) hmma_gemm_kernel(
    const float* __restrict__ patient,
    const float* __restrict__ atc4,
    const float* __restrict__ W1,
    const float* __restrict__ b1)
{
    __shared__ __half As[2][128 * GTP];   // 20.5 KB
    __shared__ __half Ws[2][128 * GTP];   // 20.5 KB

    const int bid = blockIdx.x;
    const int tid = threadIdx.x;

    const float* A;
    __half* dst;
    int LDA, m0, n0, kA0, kW0;
    bool add_b1;

    if (bid < 64) {                   // hm
        A = atc4;  LDA = MDn;  dst = g_hm;
        m0 = (bid & 15) * 128;        // v
        n0 = (bid >> 4) * 128;        // h
        kA0 = 0;  kW0 = PDn;
        add_b1 = false;
    } else {                          // hp split-K2
        int t = bid - 64;             // 0..15
        int s = t & 1;
        A = patient;  LDA = PDn;  dst = g_hp2 + s * (Bn * Hn);
        m0 = ((t >> 1) & 1) * 128;    // b
        n0 = (t >> 2) * 128;          // h
        kA0 = s * 512;  kW0 = s * 512;
        add_b1 = (s == 0);
    }

    const int wid = tid >> 5, lane = tid & 31;
    const int g = lane >> 2, t4 = lane & 3;
    const int wm = wid & 1, wn = wid >> 1;   // 2 x 4 warps; warp tile 64m x 32n

    // ldmatrix lane address bases (in halves, within a buffer).
    const int lrow = lane & 7;
    const int grp  = lane >> 3;
    // A groups: row += (grp&1)*8, col += (grp>>1)*8  -> r0..r3 = a0..a3
    const int baseA_h = (wm * 64 + lrow + (grp & 1) * 8) * GTP + (grp >> 1) * 8;
    // B groups: row += (grp>>1)*8, col += (grp&1)*8  -> r0..r3 = b[2j],b[2j+1]
    const int baseB_h = (wn * 32 + lrow + (grp >> 1) * 8) * GTP + (grp & 1) * 8;

    const unsigned asU = (unsigned)__cvta_generic_to_shared(&As[0][0]);
    const unsigned wsU = (unsigned)__cvta_generic_to_shared(&Ws[0][0]);
    const unsigned bufStride = 128 * GTP * 2;   // bytes

    float acc[4][4][4];
    #pragma unroll
    for (int i = 0; i < 4; i++)
        #pragma unroll
        for (int j = 0; j < 4; j++)
            #pragma unroll
            for (int c = 0; c < 4; c++) acc[i][j][c] = 0.0f;

    // Staging: chunk = 128 rows x 32 k fp32 per operand; 4 float4 per thread.
    const int sr = tid >> 3;          // row 0..31 (+32 per it)... idx-based below
    const int sq = tid & 7;           // float4 col 0..7

    float4 fA[4], fW[4];
    auto ldg = [&](int ch) {
        int k0 = ch * 32;
        #pragma unroll
        for (int it = 0; it < 4; it++) {
            int r = sr + it * 32;
            fA[it] = *(const float4*)(A  + (size_t)(m0 + r) * LDA  + kA0 + k0 + sq * 4);
            fW[it] = *(const float4*)(W1 + (size_t)(n0 + r) * W1LD + kW0 + k0 + sq * 4);
        }
    };
    auto sts = [&](int buf) {
        #pragma unroll
        for (int it = 0; it < 4; it++) {
            int r = sr + it * 32;
            __half ha[4] = { __float2half_rn(fA[it].x), __float2half_rn(fA[it].y),
                             __float2half_rn(fA[it].z), __float2half_rn(fA[it].w) };
            __half hw[4] = { __float2half_rn(fW[it].x), __float2half_rn(fW[it].y),
                             __float2half_rn(fW[it].z), __float2half_rn(fW[it].w) };
            *(uint2*)&As[buf][r * GTP + sq * 4] = *(uint2*)ha;
            *(uint2*)&Ws[buf][r * GTP + sq * 4] = *(uint2*)hw;
        }
    };

    const int NCH = 512 / 32;         // 16
    ldg(0);
    sts(0);
    ldg(1);
    __syncthreads();

    for (int c = 0; c < NCH; c++) {
        const int cur = c & 1;
        if (c + 1 < NCH) {
            sts(cur ^ 1);             // chunk c+1 (regs loaded at c-1)
            if (c + 2 < NCH) ldg(c + 2);
        }

        const unsigned aBase = asU + cur * bufStride + baseA_h * 2;
        const unsigned bBase = wsU + cur * bufStride + baseB_h * 2;

        #pragma unroll
        for (int ks = 0; ks < 2; ks++) {
            const int kOff = ks * 16 * 2;     // bytes
            unsigned a[4][4], b[4][2];
            #pragma unroll
            for (int mi = 0; mi < 4; mi++)
                ldsm_x4(a[mi][0], a[mi][1], a[mi][2], a[mi][3],
                        aBase + mi * (16 * GTP * 2) + kOff);
            ldsm_x4(b[0][0], b[0][1], b[1][0], b[1][1], bBase + kOff);
            ldsm_x4(b[2][0], b[2][1], b[3][0], b[3][1],
                    bBase + 16 * GTP * 2 + kOff);
            #pragma unroll
            for (int mi = 0; mi < 4; mi++)
                #pragma unroll
                for (int j = 0; j < 4; j++)
                    mma_16816(acc[mi][j], a[mi][0], a[mi][1], a[mi][2], a[mi][3],
                              b[j][0], b[j][1]);
        }
        __syncthreads();
    }

    // Epilogue: rows = m (v|b), cols = h; fp16 half2 stores.
    #pragma unroll
    for (int mi = 0; mi < 4; mi++) {
        int r0 = m0 + wm * 64 + mi * 16 + g, r1 = r0 + 8;
        #pragma unroll
        for (int j = 0; j < 4; j++) {
            int cn = n0 + wn * 32 + j * 8 + 2 * t4;
            float x0 = acc[mi][j][0], x1 = acc[mi][j][1];
            float x2 = acc[mi][j][2], x3 = acc[mi][j][3];
            if (add_b1) {
                float2 bb = *(const float2*)&b1[cn];
                x0 += bb.x; x1 += bb.y; x2 += bb.x; x3 += bb.y;
            }
            *(__half2*)&dst[(size_t)r0 * Hn + cn] = __floats2half2_rn(x0, x1);
            *(__half2*)&dst[(size_t)r1 * Hn + cn] = __floats2half2_rn(x2, x3);
        }
    }
}

// ---------------------------------------------------------------------------
// Score (R10 verbatim, measured 62.9us): hybrid MUFU/FMA-pipe tanh + HMMA.
// ---------------------------------------------------------------------------
__global__ void __launch_bounds__(128, 8) score_kernel(
    const float* __restrict__ w2, const float* __restrict__ b2p,
    float* __restrict__ out)
{
    __shared__ __half hm_sh[64 * 72];
    __shared__ __half hp_sh[8 * 72];
    __shared__ __half w2h_sh[Hn];

    const int tid  = threadIdx.x;
    const int v0   = blockIdx.x * 64;
    const int b0   = blockIdx.y * 8;
    const int lane = tid & 31;
    const int g    = lane >> 2;
    const int t    = lane & 3;
    const int vbase = (tid >> 5) * 16;

    {   // w2 -> fp16 once (covered by first __syncthreads)
        float4 w = ((const float4*)w2)[tid];
        __half h4[4] = { __float2half_rn(w.x), __float2half_rn(w.y),
                         __float2half_rn(w.z), __float2half_rn(w.w) };
        *(uint2*)&w2h_sh[tid * 4] = *(uint2*)h4;
    }

    float acc[8][4];
    #pragma unroll
    for (int b = 0; b < 8; b++)
        #pragma unroll
        for (int c = 0; c < 4; c++) acc[b][c] = 0.0f;

    for (int h0 = 0; h0 < Hn; h0 += 64) {
        __syncthreads();
        #pragma unroll
        for (int r = 0; r < 4; r++) {   // hm [64v x 64h]
            int idx = tid + r * 128;
            int vv = idx >> 3, q = idx & 7;
            uint4 m = *(const uint4*)(g_hm + (size_t)(v0 + vv) * Hn + h0 + q * 8);
            *(uint4*)&hm_sh[vv * 72 + q * 8] = m;
        }
        if (tid < 64) {                 // hp [8b x 64h] = slice0 + slice1
            int b = tid >> 3, q = tid & 7;
            size_t off = (size_t)(b0 + b) * Hn + h0 + q * 8;
            uint4 x = *(const uint4*)(g_hp2 + off);
            uint4 y = *(const uint4*)(g_hp2 + Bn * Hn + off);
            uint4 z;
            z.x = hadd2u(x.x, y.x);  z.y = hadd2u(x.y, y.y);
            z.z = hadd2u(x.z, y.z);  z.w = hadd2u(x.w, y.w);
            *(uint4*)&hp_sh[b * 72 + q * 8] = z;
        }
        __syncthreads();

        const __half* hmr0 = &hm_sh[(vbase + g) * 72];
        const __half* hmr1 = &hm_sh[(vbase + g + 8) * 72];

        #pragma unroll
        for (int c = 0; c < 4; c++) {
            const int hb = c * 16;
            unsigned m00 = *(const unsigned*)&hmr0[hb + 2 * t];
            unsigned m10 = *(const unsigned*)&hmr1[hb + 2 * t];
            unsigned m01 = *(const unsigned*)&hmr0[hb + 2 * t + 8];
            unsigned m11 = *(const unsigned*)&hmr1[hb + 2 * t + 8];
            unsigned bw0 = *(const unsigned*)&w2h_sh[h0 + hb + 2 * t];
            unsigned bw1 = *(const unsigned*)&w2h_sh[h0 + hb + 2 * t + 8];
            #pragma unroll
            for (int b = 0; b < 8; b++) {
                unsigned p0 = *(const unsigned*)&hp_sh[b * 72 + hb + 2 * t];
                unsigned p1 = *(const unsigned*)&hp_sh[b * 72 + hb + 2 * t + 8];
                unsigned x0 = hadd2u(m00, p0);
                unsigned x1 = hadd2u(m10, p0);
                unsigned x2 = hadd2u(m01, p1);
                unsigned x3 = hadd2u(m11, p1);
                unsigned a0 = tanh2_f16(x0);
                unsigned a1 = tanh2_fma(x1);
                unsigned a2 = tanh2_f16(x2);
                unsigned a3 = ((b & 1) == 0) ? tanh2_fma(x3) : tanh2_f16(x3);
                mma_16816(acc[b], a0, a1, a2, a3, bw0, bw1);
            }
        }
    }

    const float b2 = *b2p;
    if (t == 0) {
        #pragma unroll
        for (int b = 0; b < 8; b++) {
            out[(size_t)(b0 + b) * Vn + v0 + vbase + g]     = acc[b][0] + b2;
            out[(size_t)(b0 + b) * Vn + v0 + vbase + g + 8] = acc[b][2] + b2;
        }
    }
}

extern "C" void kernel_launch(void* const* d_in, const int* in_sizes, int n_in,
                              void* d_out, int out_size) {
    const float* patient = (const float*)d_in[0];  // [B, PD]
    const float* atc4    = (const float*)d_in[1];  // [V, MD]
    const float* W1      = (const float*)d_in[2];  // [H, PD+MD]
    const float* b1      = (const float*)d_in[3];  // [H]
    const float* w2      = (const float*)d_in[4];  // [H]
    const float* b2      = (const float*)d_in[5];  // scalar
    float* out = (float*)d_out;                    // [B, V]

    hmma_gemm_kernel<<<80, 256>>>(patient, atc4, W1, b1);

    dim3 grid(Vn / 64, Bn / 8);    // 1024 blocks
    score_kernel<<<grid, 128>>>(w2, b2, out);
}

// round 12
// speedup vs baseline: 1.4898x; 1.0572x over previous
#include <cuda_runtime.h>
#include <cuda_fp16.h>
#include <cstdint>

#define Bn  256
#define Vn  2048
#define PDn 1024
#define MDn 512
#define Hn  512
#define W1LD (PDn + MDn)

#define GTP 40   // GEMM smem row stride (halves)
#define HPP 520  // score hp row stride (halves)

// Intermediates (device globals; no allocations).
__device__ __half g_hm[Vn * Hn];          // [v][h]
__device__ __half g_hp2[2 * Bn * Hn];     // split-K2 slices, [b][h]; b1 in slice 0

__device__ __forceinline__ unsigned tanh2_f16(unsigned x) {
    unsigned y;
    asm("tanh.approx.f16x2 %0, %1;" : "=r"(y) : "r"(x));
    return y;
}
__device__ __forceinline__ unsigned hadd2u(unsigned a, unsigned b) {
    unsigned d;
    asm("add.rn.f16x2 %0, %1, %2;" : "=r"(d) : "r"(a), "r"(b));
    return d;
}

// tanh on the FMA pipe (R10-proven): 12 f16x2 ops, no cvt/mov/div.
__device__ __forceinline__ unsigned tanh2_fma(unsigned xu) {
    __half2 x = *(__half2*)&xu;
    __half2 xc = __hmin2(__hmax2(x, __float2half2_rn(-2.75f)),
                         __float2half2_rn(2.75f));
    __half2 u = __hmul2(xc, xc);
    __half2 s = __hfma2(u, __float2half2_rn(0.26446280f),
                           __float2half2_rn(-1.0f));
    __half2 p = __hfma2(__float2half2_rn(-0.0224000f), s,
                        __float2half2_rn( 0.0371840f));
    p = __hfma2(p, s, __float2half2_rn(-0.0164160f));
    p = __hfma2(p, s, __float2half2_rn( 0.0272720f));
    p = __hfma2(p, s, __float2half2_rn(-0.0733200f));
    p = __hfma2(p, s, __float2half2_rn( 0.1221940f));
    p = __hfma2(p, s, __float2half2_rn(-0.2074220f));
    p = __hfma2(p, s, __float2half2_rn( 0.4935290f));
    __half2 y = __hmul2(xc, p);
    return *(unsigned*)&y;
}

__device__ __forceinline__ void mma_16816(float c[4],
    unsigned a0, unsigned a1, unsigned a2, unsigned a3,
    unsigned b0, unsigned b1)
{
    asm volatile(
        "mma.sync.aligned.m16n8k16.row.col.f32.f16.f16.f32 "
        "{%0,%1,%2,%3}, {%4,%5,%6,%7}, {%8,%9}, {%0,%1,%2,%3};"
        : "+f"(c[0]), "+f"(c[1]), "+f"(c[2]), "+f"(c[3])
        : "r"(a0), "r"(a1), "r"(a2), "r"(a3), "r"(b0), "r"(b1));
}
__device__ __forceinline__ void ldsm_x4(unsigned& r0, unsigned& r1,
                                        unsigned& r2, unsigned& r3,
                                        unsigned addr) {
    asm volatile("ldmatrix.sync.aligned.m8n8.x4.shared.b16 {%0,%1,%2,%3}, [%4];"
        : "=r"(r0), "=r"(r1), "=r"(r2), "=r"(r3) : "r"(addr));
}
__device__ __forceinline__ void cp_async16(unsigned smem, const void* gptr) {
    asm volatile("cp.async.cg.shared.global [%0], [%1], 16;"
        :: "r"(smem), "l"(gptr) : "memory");
}

// ---------------------------------------------------------------------------
// HMMA GEMM (R11 verbatim, measured ~10.7us). 80 blocks x 256 thr,
// tile 128m x 128h, K=512; ldmatrix fragments; double-buffered smem.
// ---------------------------------------------------------------------------
__global__ void __launch_bounds__(256) hmma_gemm_kernel(
    const float* __restrict__ patient,
    const float* __restrict__ atc4,
    const float* __restrict__ W1,
    const float* __restrict__ b1)
{
    __shared__ __half As[2][128 * GTP];
    __shared__ __half Ws[2][128 * GTP];

    const int bid = blockIdx.x;
    const int tid = threadIdx.x;

    const float* A;
    __half* dst;
    int LDA, m0, n0, kA0, kW0;
    bool add_b1;

    if (bid < 64) {                   // hm
        A = atc4;  LDA = MDn;  dst = g_hm;
        m0 = (bid & 15) * 128;
        n0 = (bid >> 4) * 128;
        kA0 = 0;  kW0 = PDn;
        add_b1 = false;
    } else {                          // hp split-K2
        int t = bid - 64;
        int s = t & 1;
        A = patient;  LDA = PDn;  dst = g_hp2 + s * (Bn * Hn);
        m0 = ((t >> 1) & 1) * 128;
        n0 = (t >> 2) * 128;
        kA0 = s * 512;  kW0 = s * 512;
        add_b1 = (s == 0);
    }

    const int wid = tid >> 5, lane = tid & 31;
    const int g = lane >> 2, t4 = lane & 3;
    const int wm = wid & 1, wn = wid >> 1;

    const int lrow = lane & 7;
    const int grp  = lane >> 3;
    const int baseA_h = (wm * 64 + lrow + (grp & 1) * 8) * GTP + (grp >> 1) * 8;
    const int baseB_h = (wn * 32 + lrow + (grp >> 1) * 8) * GTP + (grp & 1) * 8;

    const unsigned asU = (unsigned)__cvta_generic_to_shared(&As[0][0]);
    const unsigned wsU = (unsigned)__cvta_generic_to_shared(&Ws[0][0]);
    const unsigned bufStride = 128 * GTP * 2;

    float acc[4][4][4];
    #pragma unroll
    for (int i = 0; i < 4; i++)
        #pragma unroll
        for (int j = 0; j < 4; j++)
            #pragma unroll
            for (int c = 0; c < 4; c++) acc[i][j][c] = 0.0f;

    const int sr = tid >> 3;
    const int sq = tid & 7;

    float4 fA[4], fW[4];
    auto ldg = [&](int ch) {
        int k0 = ch * 32;
        #pragma unroll
        for (int it = 0; it < 4; it++) {
            int r = sr + it * 32;
            fA[it] = *(const float4*)(A  + (size_t)(m0 + r) * LDA  + kA0 + k0 + sq * 4);
            fW[it] = *(const float4*)(W1 + (size_t)(n0 + r) * W1LD + kW0 + k0 + sq * 4);
        }
    };
    auto sts = [&](int buf) {
        #pragma unroll
        for (int it = 0; it < 4; it++) {
            int r = sr + it * 32;
            __half ha[4] = { __float2half_rn(fA[it].x), __float2half_rn(fA[it].y),
                             __float2half_rn(fA[it].z), __float2half_rn(fA[it].w) };
            __half hw[4] = { __float2half_rn(fW[it].x), __float2half_rn(fW[it].y),
                             __float2half_rn(fW[it].z), __float2half_rn(fW[it].w) };
            *(uint2*)&As[buf][r * GTP + sq * 4] = *(uint2*)ha;
            *(uint2*)&Ws[buf][r * GTP + sq * 4] = *(uint2*)hw;
        }
    };

    const int NCH = 512 / 32;
    ldg(0);
    sts(0);
    ldg(1);
    __syncthreads();

    for (int c = 0; c < NCH; c++) {
        const int cur = c & 1;
        if (c + 1 < NCH) {
            sts(cur ^ 1);
            if (c + 2 < NCH) ldg(c + 2);
        }

        const unsigned aBase = asU + cur * bufStride + baseA_h * 2;
        const unsigned bBase = wsU + cur * bufStride + baseB_h * 2;

        #pragma unroll
        for (int ks = 0; ks < 2; ks++) {
            const int kOff = ks * 16 * 2;
            unsigned a[4][4], b[4][2];
            #pragma unroll
            for (int mi = 0; mi < 4; mi++)
                ldsm_x4(a[mi][0], a[mi][1], a[mi][2], a[mi][3],
                        aBase + mi * (16 * GTP * 2) + kOff);
            ldsm_x4(b[0][0], b[0][1], b[1][0], b[1][1], bBase + kOff);
            ldsm_x4(b[2][0], b[2][1], b[3][0], b[3][1],
                    bBase + 16 * GTP * 2 + kOff);
            #pragma unroll
            for (int mi = 0; mi < 4; mi++)
                #pragma unroll
                for (int j = 0; j < 4; j++)
                    mma_16816(acc[mi][j], a[mi][0], a[mi][1], a[mi][2], a[mi][3],
                              b[j][0], b[j][1]);
        }
        __syncthreads();
    }

    #pragma unroll
    for (int mi = 0; mi < 4; mi++) {
        int r0 = m0 + wm * 64 + mi * 16 + g, r1 = r0 + 8;
        #pragma unroll
        for (int j = 0; j < 4; j++) {
            int cn = n0 + wn * 32 + j * 8 + 2 * t4;
            float x0 = acc[mi][j][0], x1 = acc[mi][j][1];
            float x2 = acc[mi][j][2], x3 = acc[mi][j][3];
            if (add_b1) {
                float2 bb = *(const float2*)&b1[cn];
                x0 += bb.x; x1 += bb.y; x2 += bb.x; x3 += bb.y;
            }
            *(__half2*)&dst[(size_t)r0 * Hn + cn] = __floats2half2_rn(x0, x1);
            *(__half2*)&dst[(size_t)r1 * Hn + cn] = __floats2half2_rn(x2, x3);
        }
    }
}

// ---------------------------------------------------------------------------
// Score: hybrid MUFU/FMA tanh + HMMA (R10 math), with:
//  - hp staged ONCE for all H (slice-sum + b1 folded), 8.3KB smem
//  - hm staged via cp.async double-buffer: chunk c+1 in flight during c
// Two syncs/chunk, zero exposed L2 latency. Block 128 thr, grid 1024.
// ---------------------------------------------------------------------------
__global__ void __launch_bounds__(128, 8) score_kernel(
    const float* __restrict__ w2, const float* __restrict__ b2p,
    float* __restrict__ out)
{
    __shared__ __half hm_sh[2][64 * 72];  // 18.4 KB double buffer
    __shared__ __half hp_sh[8 * HPP];     // 8.3 KB, full H per b
    __shared__ __half w2h_sh[Hn];

    const int tid  = threadIdx.x;
    const int v0   = blockIdx.x * 64;
    const int b0   = blockIdx.y * 8;
    const int lane = tid & 31;
    const int g    = lane >> 2;
    const int t    = lane & 3;
    const int vbase = (tid >> 5) * 16;

    {   // w2 -> fp16 once
        float4 w = ((const float4*)w2)[tid];
        __half h4[4] = { __float2half_rn(w.x), __float2half_rn(w.y),
                         __float2half_rn(w.z), __float2half_rn(w.w) };
        *(uint2*)&w2h_sh[tid * 4] = *(uint2*)h4;
    }
    // hp full-H staging: 8b x 512h, slice0+slice1 (b1 pre-folded in slice 0).
    #pragma unroll
    for (int r = 0; r < 4; r++) {
        int idx = tid + r * 128;       // 0..511
        int b = idx >> 6, q = idx & 63;
        size_t off = (size_t)(b0 + b) * Hn + q * 8;
        uint4 x = *(const uint4*)(g_hp2 + off);
        uint4 y = *(const uint4*)(g_hp2 + Bn * Hn + off);
        uint4 z;
        z.x = hadd2u(x.x, y.x);  z.y = hadd2u(x.y, y.y);
        z.z = hadd2u(x.z, y.z);  z.w = hadd2u(x.w, y.w);
        *(uint4*)&hp_sh[b * HPP + q * 8] = z;
    }

    // cp.async staging map for hm chunks: 512 x 16B per chunk, 4 per thread.
    const unsigned hmU = (unsigned)__cvta_generic_to_shared(&hm_sh[0][0]);
    const unsigned hmBuf = 64 * 72 * 2;   // bytes per buffer
    const int svv = tid >> 3;             // v row 0..15 (+16 per r)
    const int sq8 = (tid & 7) * 8;        // h col (halves)

    auto stage_hm = [&](int ch) {
        int buf = ch & 1;
        int h0 = ch * 64;
        #pragma unroll
        for (int r = 0; r < 4; r++) {
            int vv = svv + r * 16;
            cp_async16(hmU + buf * hmBuf + (vv * 72 + sq8) * 2,
                       g_hm + (size_t)(v0 + vv) * Hn + h0 + sq8);
        }
        asm volatile("cp.async.commit_group;" ::: "memory");
    };

    float acc[8][4];
    #pragma unroll
    for (int b = 0; b < 8; b++)
        #pragma unroll
        for (int c = 0; c < 4; c++) acc[b][c] = 0.0f;

    stage_hm(0);
    stage_hm(1);

    for (int ch = 0; ch < 8; ch++) {
        if (ch < 7)
            asm volatile("cp.async.wait_group 1;" ::: "memory");
        else
            asm volatile("cp.async.wait_group 0;" ::: "memory");
        __syncthreads();   // chunk ch visible to all warps (also covers hp/w2 on ch==0)

        const __half* hmb = hm_sh[ch & 1];
        const __half* hmr0 = &hmb[(vbase + g) * 72];
        const __half* hmr1 = &hmb[(vbase + g + 8) * 72];
        const int h0 = ch * 64;

        #pragma unroll
        for (int c = 0; c < 4; c++) {
            const int hb = c * 16;
            unsigned m00 = *(const unsigned*)&hmr0[hb + 2 * t];
            unsigned m10 = *(const unsigned*)&hmr1[hb + 2 * t];
            unsigned m01 = *(const unsigned*)&hmr0[hb + 2 * t + 8];
            unsigned m11 = *(const unsigned*)&hmr1[hb + 2 * t + 8];
            unsigned bw0 = *(const unsigned*)&w2h_sh[h0 + hb + 2 * t];
            unsigned bw1 = *(const unsigned*)&w2h_sh[h0 + hb + 2 * t + 8];
            #pragma unroll
            for (int b = 0; b < 8; b++) {
                const __half* hpr = &hp_sh[b * HPP + h0 + hb];
                unsigned p0 = *(const unsigned*)&hpr[2 * t];
                unsigned p1 = *(const unsigned*)&hpr[2 * t + 8];
                unsigned x0 = hadd2u(m00, p0);
                unsigned x1 = hadd2u(m10, p0);
                unsigned x2 = hadd2u(m01, p1);
                unsigned x3 = hadd2u(m11, p1);
                unsigned a0 = tanh2_f16(x0);
                unsigned a1 = tanh2_fma(x1);
                unsigned a2 = tanh2_f16(x2);
                unsigned a3 = ((b & 1) == 0) ? tanh2_fma(x3) : tanh2_f16(x3);
                mma_16816(acc[b], a0, a1, a2, a3, bw0, bw1);
            }
        }
        __syncthreads();   // all warps done reading buf before it's refilled
        if (ch + 2 < 8) stage_hm(ch + 2);
    }

    const float b2 = *b2p;
    if (t == 0) {
        #pragma unroll
        for (int b = 0; b < 8; b++) {
            out[(size_t)(b0 + b) * Vn + v0 + vbase + g]     = acc[b][0] + b2;
            out[(size_t)(b0 + b) * Vn + v0 + vbase + g + 8] = acc[b][2] + b2;
        }
    }
}

extern "C" void kernel_launch(void* const* d_in, const int* in_sizes, int n_in,
                              void* d_out, int out_size) {
    const float* patient = (const float*)d_in[0];  // [B, PD]
    const float* atc4    = (const float*)d_in[1];  // [V, MD]
    const float* W1      = (const float*)d_in[2];  // [H, PD+MD]
    const float* b1      = (const float*)d_in[3];  // [H]
    const float* w2      = (const float*)d_in[4];  // [H]
    const float* b2      = (const float*)d_in[5];  // scalar
    float* out = (float*)d_out;                    // [B, V]

    hmma_gemm_kernel<<<80, 256>>>(patient, atc4, W1, b1);

    dim3 grid(Vn / 64, Bn / 8);    // 1024 blocks
    score_kernel<<<grid, 128>>>(w2, b2, out);
}